// round 16
// baseline (speedup 1.0000x reference)
#include <cuda_runtime.h>
#include <cuda_bf16.h>
#include <cuda_fp16.h>
#include <stdint.h>

// Problem constants: N=100000, E=1600000, IN=128, H=OUT=64
#define NMAX 100000
#define EMAX 1600000
#define HF   64

// Scratch (allocation-free device globals)
__device__ __half g_hs [(size_t)NMAX * HF];   // messages, fp16
__device__ float  g_acc[(size_t)NMAX * HF];
__device__ float  g_dinv[NMAX];
__device__ int    g_deg [NMAX];
__device__ int    g_off [NMAX + 1];
__device__ int    g_cursor[NMAX];
__device__ int    g_adj [EMAX];
__device__ int    g_bsum[256];
__device__ double g_sums[3 * 2 * HF];         // per-layer slots: [layer][sum|sumsq][64]
__device__ float  g_part[64 * 128];           // spread stats partials [slot][sum64|sq64]
// Pre-split weights, transposed: W^T [64 x K] bf16 hi/lo.
__device__ __nv_bfloat16 g_wThi[16384];
__device__ __nv_bfloat16 g_wTlo[16384];

// ---------------------------------------------------------------------------
// MMA helpers (HMMA bf16 — plain sm_80+ PTX)
// ---------------------------------------------------------------------------
__device__ __forceinline__ uint32_t smem_u32(const void* p) {
    uint32_t a;
    asm("{ .reg .u64 t; cvta.to.shared.u64 t, %1; cvt.u32.u64 %0, t; }"
        : "=r"(a) : "l"(p));
    return a;
}

__device__ __forceinline__ void ldsm_x4(uint32_t* r, uint32_t addr) {
    asm volatile("ldmatrix.sync.aligned.m8n8.x4.shared.b16 {%0,%1,%2,%3}, [%4];"
                 : "=r"(r[0]), "=r"(r[1]), "=r"(r[2]), "=r"(r[3]) : "r"(addr));
}

__device__ __forceinline__ void ldsm_x2(uint32_t* r, uint32_t addr) {
    asm volatile("ldmatrix.sync.aligned.m8n8.x2.shared.b16 {%0,%1}, [%2];"
                 : "=r"(r[0]), "=r"(r[1]) : "r"(addr));
}

__device__ __forceinline__ void mma_bf16(float* c, const uint32_t* a, const uint32_t* b) {
    asm volatile("mma.sync.aligned.m16n8k16.row.col.f32.bf16.bf16.f32 "
                 "{%0,%1,%2,%3}, {%4,%5,%6,%7}, {%8,%9}, {%0,%1,%2,%3};"
                 : "+f"(c[0]), "+f"(c[1]), "+f"(c[2]), "+f"(c[3])
                 : "r"(a[0]), "r"(a[1]), "r"(a[2]), "r"(a[3]),
                   "r"(b[0]), "r"(b[1]));
}

__device__ __forceinline__ uint32_t pack_bf2(__nv_bfloat16 lo, __nv_bfloat16 hi) {
    __nv_bfloat162 t(lo, hi);
    return *(uint32_t*)&t;
}

__device__ __forceinline__ uint2 split4(float4 v) {
    __nv_bfloat16 h0 = __float2bfloat16(v.x), h1 = __float2bfloat16(v.y);
    __nv_bfloat16 h2 = __float2bfloat16(v.z), h3 = __float2bfloat16(v.w);
    return make_uint2(pack_bf2(h0, h1), pack_bf2(h2, h3));
}

__device__ __forceinline__ void acc8(float2& t0, float2& t1, float2& t2, float2& t3,
                                     uint4 q) {
    float2 a = __half22float2(*(__half2*)&q.x);
    float2 b = __half22float2(*(__half2*)&q.y);
    float2 cc = __half22float2(*(__half2*)&q.z);
    float2 d = __half22float2(*(__half2*)&q.w);
    t0.x += a.x;  t0.y += a.y;
    t1.x += b.x;  t1.y += b.y;
    t2.x += cc.x; t2.y += cc.y;
    t3.x += d.x;  t3.y += d.y;
}

// Compute BN scale/shift for one feature from a g_sums slot.
__device__ __forceinline__ void bn_param(int soff, int f, double inv_n,
                                         const float* gam, const float* bet,
                                         float& sc, float& sh) {
    float mu  = (float)(g_sums[soff + f] * inv_n);
    float var = (float)(g_sums[soff + 64 + f] * inv_n) - mu * mu;
    float rs  = rsqrtf(var + 1e-5f);
    sc = rs * gam[f];
    sh = bet[f] - mu * sc;
}

// ---------------------------------------------------------------------------
// Setup: weight pre-split + deg/sums/partials reset (one launch)
// ---------------------------------------------------------------------------
__global__ void setup_kernel(const float* __restrict__ W1,
                             const float* __restrict__ W2,
                             const float* __restrict__ W3, int n)
{
    int i = blockIdx.x * blockDim.x + threadIdx.x;
    if (i < 16384) {
        const float* W;
        int off, K;
        if (i < 8192)       { W = W1; off = 0;     K = 128; }
        else if (i < 12288) { W = W2; off = 8192;  K = 64;  }
        else                { W = W3; off = 12288; K = 64;  }
        int j  = i - off;
        int nn = j / K;
        int k  = j - nn * K;
        float w = W[(size_t)k * 64 + nn];
        __nv_bfloat16 hi = __float2bfloat16(w);
        __nv_bfloat16 lo = __float2bfloat16(w - __bfloat162float(hi));
        g_wThi[i] = hi;
        g_wTlo[i] = lo;
    }
    if (i < n) g_deg[i] = 0;
    if (i < 384) g_sums[i] = 0.0;
    if (i < 8192) g_part[i] = 0.f;
}

// ---------------------------------------------------------------------------
// Edge pass 1: degree count — 4 edges/thread via int4 (MLP=4)
// ---------------------------------------------------------------------------
__global__ void deg_count_kernel(const int* __restrict__ dst, int E) {
    int i = (blockIdx.x * blockDim.x + threadIdx.x) * 4;
    if (i + 3 < E) {
        int4 d = *(const int4*)(dst + i);
        atomicAdd(&g_deg[d.x], 1);
        atomicAdd(&g_deg[d.y], 1);
        atomicAdd(&g_deg[d.z], 1);
        atomicAdd(&g_deg[d.w], 1);
    } else {
        for (int j = i; j < E; j++) atomicAdd(&g_deg[dst[j]], 1);
    }
}

// ---------------------------------------------------------------------------
// Scan: block sums, then final scan (block prefix computed in-kernel)
// ---------------------------------------------------------------------------
__global__ void scan_bsum_kernel(int n) {
    __shared__ int sh[256];
    int b = blockIdx.x, t = threadIdx.x;
    int base = b * 1024;
    int s = 0;
    for (int i = t; i < 1024; i += 256) {
        int idx = base + i;
        if (idx < n) s += g_deg[idx];
    }
    sh[t] = s;
    __syncthreads();
    for (int o = 128; o > 0; o >>= 1) {
        if (t < o) sh[t] += sh[t + o];
        __syncthreads();
    }
    if (t == 0) g_bsum[b] = sh[0];
}

__global__ void scan_final_kernel(int n, int nb, int E) {
    __shared__ int sh[1024];
    __shared__ int pre[128];
    int b = blockIdx.x, t = threadIdx.x;

    if (t < 128) pre[t] = (t < b && t < nb) ? g_bsum[t] : 0;
    __syncthreads();
    if (t < 64) pre[t] += pre[t + 64];
    __syncthreads();
    if (t < 32) {
        int s = pre[t] + pre[t + 32];
#pragma unroll
        for (int o = 16; o > 0; o >>= 1)
            s += __shfl_down_sync(0xFFFFFFFFu, s, o);
        if (t == 0) pre[0] = s;
    }
    __syncthreads();
    const int bpre = pre[0];

    int idx = b * 1024 + t;
    int v = (idx < n) ? g_deg[idx] : 0;
    sh[t] = v;
    for (int o = 1; o < 1024; o <<= 1) {
        __syncthreads();
        int u = (t >= o) ? sh[t - o] : 0;
        __syncthreads();
        sh[t] += u;
    }
    __syncthreads();
    if (idx < n) {
        int ex = sh[t] - v + bpre;
        g_off[idx]    = ex;
        g_cursor[idx] = ex;
        g_dinv[idx]   = rsqrtf((float)(v + 1));
    }
    if (b == nb - 1 && t == 1023) g_off[n] = E;
}

// ---------------------------------------------------------------------------
// Edge pass 2: CSR fill — 4 edges/thread via int4 (MLP=4)
// ---------------------------------------------------------------------------
__global__ void fill_adj_kernel(const int* __restrict__ src,
                                const int* __restrict__ dst, int E) {
    int i = (blockIdx.x * blockDim.x + threadIdx.x) * 4;
    if (i + 3 < E) {
        int4 s = *(const int4*)(src + i);
        int4 d = *(const int4*)(dst + i);
        int p0 = atomicAdd(&g_cursor[d.x], 1);
        int p1 = atomicAdd(&g_cursor[d.y], 1);
        int p2 = atomicAdd(&g_cursor[d.z], 1);
        int p3 = atomicAdd(&g_cursor[d.w], 1);
        g_adj[p0] = s.x;
        g_adj[p1] = s.y;
        g_adj[p2] = s.z;
        g_adj[p3] = s.w;
    } else {
        for (int j = i; j < E; j++) {
            int pos = atomicAdd(&g_cursor[dst[j]], 1);
            g_adj[pos] = src[j];
        }
    }
}

// ---------------------------------------------------------------------------
// HMMA GEMM (proven): hs[row] = (transform(in[row]) @ W) * dinv[row]
// Split-bf16 3-pass, fp32 accumulation. Weights pre-split (global bf16).
// CTA tile 128x64, 512 threads = 16 warps (8x2 of 16x32 tiles), 2 CTAs/SM.
// TRANS: BN params computed in-CTA from previous layer's g_sums slot.
// ---------------------------------------------------------------------------
template<int K, bool TRANS>
__global__ void __launch_bounds__(512, 2)
gemm_mma_kernel(const float* __restrict__ Xin,
                int woff, int soff,
                const float* __restrict__ gam,
                const float* __restrict__ bet,
                const float* __restrict__ alpha,
                int n)
{
    constexpr int LDA  = K + 8;
    constexpr int A_HI = 0;
    constexpr int A_LO = 128 * LDA;
    constexpr int B_HI = 256 * LDA;
    constexpr int B_LO = 256 * LDA + 64 * LDA;

    extern __shared__ __nv_bfloat16 smem[];
    __shared__ float sScale[64], sShift[64];
    const uint32_t sb = smem_u32(smem);
    const int tid = threadIdx.x;
    const int wid = tid >> 5, lid = tid & 31;
    const int rowBase = blockIdx.x * 128;

    if (TRANS) {
        if (tid < 64) {
            float sc, sh;
            bn_param(soff, tid, 1.0 / (double)n, gam, bet, sc, sh);
            sScale[tid] = sc;
            sShift[tid] = sh;
        }
        __syncthreads();
    }

    const float* X = TRANS ? g_acc : Xin;
    for (int i = tid; i < 128 * (K / 4); i += 512) {
        int r  = i / (K / 4);
        int k0 = (i % (K / 4)) * 4;
        float4 v = make_float4(0.f, 0.f, 0.f, 0.f);
        int row = rowBase + r;
        if (row < n) {
            v = *(const float4*)(X + (size_t)row * K + k0);
            if (TRANS) {
                float t;
                t = v.x * sScale[k0+0] + sShift[k0+0]; v.x = (t >= 0.f) ? t : t * alpha[k0+0];
                t = v.y * sScale[k0+1] + sShift[k0+1]; v.y = (t >= 0.f) ? t : t * alpha[k0+1];
                t = v.z * sScale[k0+2] + sShift[k0+2]; v.z = (t >= 0.f) ? t : t * alpha[k0+2];
                t = v.w * sScale[k0+3] + sShift[k0+3]; v.w = (t >= 0.f) ? t : t * alpha[k0+3];
            }
        }
        uint2 hi = split4(v);
        float4 res = make_float4(
            v.x - __bfloat162float(__float2bfloat16(v.x)),
            v.y - __bfloat162float(__float2bfloat16(v.y)),
            v.z - __bfloat162float(__float2bfloat16(v.z)),
            v.w - __bfloat162float(__float2bfloat16(v.w)));
        uint2 lo = split4(res);
        *(uint2*)(smem + A_HI + r * LDA + k0) = hi;
        *(uint2*)(smem + A_LO + r * LDA + k0) = lo;
    }

    for (int i = tid; i < 64 * (K / 8); i += 512) {
        int nn = i / (K / 8);
        int k0 = (i % (K / 8)) * 8;
        uint4 hi = *(const uint4*)(g_wThi + woff + nn * K + k0);
        uint4 lo = *(const uint4*)(g_wTlo + woff + nn * K + k0);
        *(uint4*)(smem + B_HI + nn * LDA + k0) = hi;
        *(uint4*)(smem + B_LO + nn * LDA + k0) = lo;
    }
    __syncthreads();

    const int warpRow = wid & 7;
    const int warpCol = wid >> 3;

    float acc[4][4];
#pragma unroll
    for (int ni = 0; ni < 4; ni++)
#pragma unroll
        for (int j = 0; j < 4; j++) acc[ni][j] = 0.f;

    const int aRow  = warpRow * 16 + (lid & 15);
    const int aKoff = (lid >> 4) * 8;
    const int bRow  = warpCol * 32 + (lid & 7);
    const int bKoff = ((lid >> 3) & 1) * 8;

#pragma unroll
    for (int k0 = 0; k0 < K; k0 += 16) {
        uint32_t aHi[4], aLo[4], bHi[4][2], bLo[4][2];
        {
            uint32_t base = (uint32_t)((aRow * LDA + k0 + aKoff) * 2);
            ldsm_x4(aHi, sb + A_HI * 2 + base);
            ldsm_x4(aLo, sb + A_LO * 2 + base);
        }
#pragma unroll
        for (int ni = 0; ni < 4; ni++) {
            uint32_t base = (uint32_t)(((bRow + ni * 8) * LDA + k0 + bKoff) * 2);
            ldsm_x2(bHi[ni], sb + B_HI * 2 + base);
            ldsm_x2(bLo[ni], sb + B_LO * 2 + base);
        }
#pragma unroll
        for (int ni = 0; ni < 4; ni++) {
            mma_bf16(acc[ni], aHi, bHi[ni]);
            mma_bf16(acc[ni], aHi, bLo[ni]);
            mma_bf16(acc[ni], aLo, bHi[ni]);
        }
    }

    const int rBase = rowBase + warpRow * 16 + (lid >> 2);
    const int cBase = warpCol * 32 + (lid & 3) * 2;
#pragma unroll
    for (int h = 0; h < 2; h++) {
        int row = rBase + h * 8;
        if (row < n) {
            float dv = g_dinv[row];
            __half* o = g_hs + (size_t)row * 64;
#pragma unroll
            for (int ni = 0; ni < 4; ni++) {
                float2 v = make_float2(acc[ni][h * 2 + 0] * dv,
                                       acc[ni][h * 2 + 1] * dv);
                *(__half2*)(o + cBase + ni * 8) = __float22half2_rn(v);
            }
        }
    }
}

// ---------------------------------------------------------------------------
// CSR gather + warp-level fused BN stats (NO barriers, spread fp32 atomics):
//   acc[v] = dinv[v] * (hs[v] + sum_{adj} hs[s])
//   warp shfl_xor(8,16) reduces sum/sumsq over its 4 node slots;
//   lanes 0-7 fire fp32 REDs into g_part[blockIdx.x & 63] (64-way spread
//   -> ~49 serialized ops/address total, invisible).
// ---------------------------------------------------------------------------
__global__ void gather_kernel(int n)
{
    int idx = blockIdx.x * blockDim.x + threadIdx.x;
    int v = idx >> 3;
    int c = idx & 7;
    int lane = threadIdx.x & 31;

    float f[8] = {0.f, 0.f, 0.f, 0.f, 0.f, 0.f, 0.f, 0.f};

    if (v < n) {
        int e0 = g_off[v];
        int e1 = g_off[v + 1];

        uint4 m = ((const uint4*)g_hs)[(size_t)v * 8 + c];  // self-loop
        float2 t0 = __half22float2(*(__half2*)&m.x);
        float2 t1 = __half22float2(*(__half2*)&m.y);
        float2 t2 = __half22float2(*(__half2*)&m.z);
        float2 t3 = __half22float2(*(__half2*)&m.w);

        int e = e0;
        for (; e + 4 <= e1; e += 4) {
            int s0 = __ldg(&g_adj[e + 0]);
            int s1 = __ldg(&g_adj[e + 1]);
            int s2 = __ldg(&g_adj[e + 2]);
            int s3 = __ldg(&g_adj[e + 3]);
            uint4 q0 = ((const uint4*)g_hs)[(size_t)s0 * 8 + c];
            uint4 q1 = ((const uint4*)g_hs)[(size_t)s1 * 8 + c];
            uint4 q2 = ((const uint4*)g_hs)[(size_t)s2 * 8 + c];
            uint4 q3 = ((const uint4*)g_hs)[(size_t)s3 * 8 + c];
            acc8(t0, t1, t2, t3, q0);
            acc8(t0, t1, t2, t3, q1);
            acc8(t0, t1, t2, t3, q2);
            acc8(t0, t1, t2, t3, q3);
        }
        for (; e < e1; e++) {
            int s = __ldg(&g_adj[e]);
            uint4 q = ((const uint4*)g_hs)[(size_t)s * 8 + c];
            acc8(t0, t1, t2, t3, q);
        }

        float dv = g_dinv[v];
        f[0] = t0.x * dv; f[1] = t0.y * dv; f[2] = t1.x * dv; f[3] = t1.y * dv;
        f[4] = t2.x * dv; f[5] = t2.y * dv; f[6] = t3.x * dv; f[7] = t3.y * dv;
        float4* out = (float4*)(g_acc + (size_t)v * 64 + c * 8);
        out[0] = make_float4(f[0], f[1], f[2], f[3]);
        out[1] = make_float4(f[4], f[5], f[6], f[7]);
    }

    // warp-level stats reduction across 4 node slots (lane bits 3,4)
    float s1[8], s2[8];
#pragma unroll
    for (int j = 0; j < 8; j++) { s1[j] = f[j]; s2[j] = f[j] * f[j]; }
#pragma unroll
    for (int j = 0; j < 8; j++) {
        s1[j] += __shfl_xor_sync(0xFFFFFFFFu, s1[j], 8);
        s2[j] += __shfl_xor_sync(0xFFFFFFFFu, s2[j], 8);
        s1[j] += __shfl_xor_sync(0xFFFFFFFFu, s1[j], 16);
        s2[j] += __shfl_xor_sync(0xFFFFFFFFu, s2[j], 16);
    }
    if (lane < 8) {
        float* base = g_part + (blockIdx.x & 63) * 128;
#pragma unroll
        for (int j = 0; j < 8; j++) {
            atomicAdd(base + lane * 8 + j,      s1[j]);
            atomicAdd(base + 64 + lane * 8 + j, s2[j]);
        }
    }
}

// ---------------------------------------------------------------------------
// Fold spread partials into a g_sums slot; re-zero g_part for next layer.
// One block, 128 threads (f<64: sums, f>=64: sumsq — matches slot layout).
// ---------------------------------------------------------------------------
__global__ void reduce_part_kernel(int soff)
{
    int f = threadIdx.x;   // 0..127
    float s = 0.f;
#pragma unroll 8
    for (int b = 0; b < 64; b++) {
        s += g_part[b * 128 + f];
        g_part[b * 128 + f] = 0.f;
    }
    g_sums[soff + f] = (double)s;
}

// ---------------------------------------------------------------------------
// Output: computes layer-3 BN params in-block, applies BN+PReLU.
// ---------------------------------------------------------------------------
__global__ void out_kernel(const float* __restrict__ gam,
                           const float* __restrict__ bet,
                           const float* __restrict__ alpha,
                           float* __restrict__ out, int n)
{
    __shared__ float sS[64], sB[64];
    if (threadIdx.x < 64) {
        float sc, sh;
        bn_param(256, threadIdx.x, 1.0 / (double)n, gam, bet, sc, sh);
        sS[threadIdx.x] = sc;
        sB[threadIdx.x] = sh;
    }
    __syncthreads();

    int idx = blockIdx.x * blockDim.x + threadIdx.x;   // float4 chunk id
    if (idx >= n * 16) return;
    int f = (idx & 15) * 4;
    float4 v = ((const float4*)g_acc)[idx];
    float t;
    t = v.x * sS[f+0] + sB[f+0]; v.x = (t >= 0.f) ? t : t * alpha[f+0];
    t = v.y * sS[f+1] + sB[f+1]; v.y = (t >= 0.f) ? t : t * alpha[f+1];
    t = v.z * sS[f+2] + sB[f+2]; v.z = (t >= 0.f) ? t : t * alpha[f+2];
    t = v.w * sS[f+3] + sB[f+3]; v.w = (t >= 0.f) ? t : t * alpha[f+3];
    ((float4*)out)[idx] = v;
}

// ---------------------------------------------------------------------------
// Launch
// ---------------------------------------------------------------------------
extern "C" void kernel_launch(void* const* d_in, const int* in_sizes, int n_in,
                              void* d_out, int out_size)
{
    const float* x   = (const float*)d_in[0];
    const int*   ei  = (const int*)  d_in[1];
    const int N = in_sizes[0] / 128;
    const int E = in_sizes[1] / 2;
    const int* src = ei;
    const int* dst = ei + E;

    const float* W1  = (const float*)d_in[2];
    const float* G1  = (const float*)d_in[4];
    const float* BE1 = (const float*)d_in[5];
    const float* A1  = (const float*)d_in[6];
    const float* W2  = (const float*)d_in[7];
    const float* G2  = (const float*)d_in[9];
    const float* BE2 = (const float*)d_in[10];
    const float* A2  = (const float*)d_in[11];
    const float* W3  = (const float*)d_in[12];
    const float* G3  = (const float*)d_in[14];
    const float* BE3 = (const float*)d_in[15];
    const float* A3  = (const float*)d_in[16];

    const int smem128 = 384 * (128 + 8) * 2;  // 104448 B
    const int smem64  = 384 * (64 + 8) * 2;   //  55296 B
    cudaFuncSetAttribute((const void*)gemm_mma_kernel<128, false>,
                         cudaFuncAttributeMaxDynamicSharedMemorySize, smem128);
    cudaFuncSetAttribute((const void*)gemm_mma_kernel<64, true>,
                         cudaFuncAttributeMaxDynamicSharedMemorySize, smem64);

    const int gN  = (N + 255) / 256;
    const int gE4 = (E / 4 + 255) / 256;
    const int gG  = (N + 127) / 128;
    const int gGa = (N * 8 + 255) / 256;
    const int gO  = (N * 16 + 255) / 256;
    const int nb  = (N + 1023) / 1024;

    // Setup + CSR build (reused by all 3 layers)
    setup_kernel     <<<gN, 256>>>(W1, W2, W3, N);
    deg_count_kernel <<<gE4, 256>>>(dst, E);
    scan_bsum_kernel <<<nb, 256>>>(N);
    scan_final_kernel<<<nb, 1024>>>(N, nb, E);
    fill_adj_kernel  <<<gE4, 256>>>(src, dst, E);

    // ---- Layer 1 ----
    gemm_mma_kernel<128, false><<<gG, 512, smem128>>>(x, 0, 0, nullptr, nullptr, nullptr, N);
    gather_kernel     <<<gGa, 256>>>(N);
    reduce_part_kernel<<<1, 128>>>(0);

    // ---- Layer 2 (BN params of layer 1 computed in-GEMM from slot 0) ----
    gemm_mma_kernel<64, true><<<gG, 512, smem64>>>(nullptr, 8192, 0, G1, BE1, A1, N);
    gather_kernel     <<<gGa, 256>>>(N);
    reduce_part_kernel<<<1, 128>>>(128);

    // ---- Layer 3 (BN params of layer 2 from slot 1) ----
    gemm_mma_kernel<64, true><<<gG, 512, smem64>>>(nullptr, 12288, 128, G2, BE2, A2, N);
    gather_kernel     <<<gGa, 256>>>(N);
    reduce_part_kernel<<<1, 128>>>(256);

    // ---- Output (BN params of layer 3 from slot 2) ----
    out_kernel<<<gO, 256>>>(G3, BE3, A3, (float*)d_out, N);
}

// round 17
// speedup vs baseline: 2.0143x; 2.0143x over previous
#include <cuda_runtime.h>
#include <cuda_bf16.h>
#include <cuda_fp16.h>
#include <stdint.h>

// Problem constants: N=100000, E=1600000, IN=128, H=OUT=64
#define NMAX 100000
#define EMAX 1600000
#define HF   64

// Scratch (allocation-free device globals)
__device__ __half g_hs [(size_t)NMAX * HF];   // messages, fp16
__device__ float  g_acc[(size_t)NMAX * HF];
__device__ float  g_dinv[NMAX];
__device__ int    g_deg [NMAX];
__device__ int    g_off [NMAX + 1];
__device__ int    g_cursor[NMAX];
__device__ int    g_adj [EMAX];
__device__ int    g_bsum[256];
__device__ double g_sums[3 * 2 * HF];         // per-layer slots: [layer][sum|sumsq][64]
// Pre-split weights, transposed: W^T [64 x K] bf16 hi/lo.
__device__ __nv_bfloat16 g_wThi[16384];
__device__ __nv_bfloat16 g_wTlo[16384];

// ---------------------------------------------------------------------------
// MMA helpers (HMMA bf16 — plain sm_80+ PTX)
// ---------------------------------------------------------------------------
__device__ __forceinline__ uint32_t smem_u32(const void* p) {
    uint32_t a;
    asm("{ .reg .u64 t; cvta.to.shared.u64 t, %1; cvt.u32.u64 %0, t; }"
        : "=r"(a) : "l"(p));
    return a;
}

__device__ __forceinline__ void ldsm_x4(uint32_t* r, uint32_t addr) {
    asm volatile("ldmatrix.sync.aligned.m8n8.x4.shared.b16 {%0,%1,%2,%3}, [%4];"
                 : "=r"(r[0]), "=r"(r[1]), "=r"(r[2]), "=r"(r[3]) : "r"(addr));
}

__device__ __forceinline__ void ldsm_x2(uint32_t* r, uint32_t addr) {
    asm volatile("ldmatrix.sync.aligned.m8n8.x2.shared.b16 {%0,%1}, [%2];"
                 : "=r"(r[0]), "=r"(r[1]) : "r"(addr));
}

__device__ __forceinline__ void mma_bf16(float* c, const uint32_t* a, const uint32_t* b) {
    asm volatile("mma.sync.aligned.m16n8k16.row.col.f32.bf16.bf16.f32 "
                 "{%0,%1,%2,%3}, {%4,%5,%6,%7}, {%8,%9}, {%0,%1,%2,%3};"
                 : "+f"(c[0]), "+f"(c[1]), "+f"(c[2]), "+f"(c[3])
                 : "r"(a[0]), "r"(a[1]), "r"(a[2]), "r"(a[3]),
                   "r"(b[0]), "r"(b[1]));
}

__device__ __forceinline__ uint32_t pack_bf2(__nv_bfloat16 lo, __nv_bfloat16 hi) {
    __nv_bfloat162 t(lo, hi);
    return *(uint32_t*)&t;
}

__device__ __forceinline__ uint2 split4(float4 v) {
    __nv_bfloat16 h0 = __float2bfloat16(v.x), h1 = __float2bfloat16(v.y);
    __nv_bfloat16 h2 = __float2bfloat16(v.z), h3 = __float2bfloat16(v.w);
    return make_uint2(pack_bf2(h0, h1), pack_bf2(h2, h3));
}

__device__ __forceinline__ void acc8(float2& t0, float2& t1, float2& t2, float2& t3,
                                     uint4 q) {
    float2 a = __half22float2(*(__half2*)&q.x);
    float2 b = __half22float2(*(__half2*)&q.y);
    float2 cc = __half22float2(*(__half2*)&q.z);
    float2 d = __half22float2(*(__half2*)&q.w);
    t0.x += a.x;  t0.y += a.y;
    t1.x += b.x;  t1.y += b.y;
    t2.x += cc.x; t2.y += cc.y;
    t3.x += d.x;  t3.y += d.y;
}

// Compute BN scale/shift for one feature from a g_sums slot.
__device__ __forceinline__ void bn_param(int soff, int f, double inv_n,
                                         const float* gam, const float* bet,
                                         float& sc, float& sh) {
    float mu  = (float)(g_sums[soff + f] * inv_n);
    float var = (float)(g_sums[soff + 64 + f] * inv_n) - mu * mu;
    float rs  = rsqrtf(var + 1e-5f);
    sc = rs * gam[f];
    sh = bet[f] - mu * sc;
}

// ---------------------------------------------------------------------------
// Setup: weight pre-split + deg/sums reset (one launch)
// ---------------------------------------------------------------------------
__global__ void setup_kernel(const float* __restrict__ W1,
                             const float* __restrict__ W2,
                             const float* __restrict__ W3, int n)
{
    int i = blockIdx.x * blockDim.x + threadIdx.x;
    if (i < 16384) {
        const float* W;
        int off, K;
        if (i < 8192)       { W = W1; off = 0;     K = 128; }
        else if (i < 12288) { W = W2; off = 8192;  K = 64;  }
        else                { W = W3; off = 12288; K = 64;  }
        int j  = i - off;
        int nn = j / K;
        int k  = j - nn * K;
        float w = W[(size_t)k * 64 + nn];
        __nv_bfloat16 hi = __float2bfloat16(w);
        __nv_bfloat16 lo = __float2bfloat16(w - __bfloat162float(hi));
        g_wThi[i] = hi;
        g_wTlo[i] = lo;
    }
    if (i < n) g_deg[i] = 0;
    if (i < 384) g_sums[i] = 0.0;
}

// ---------------------------------------------------------------------------
// Edge pass 1: degree count — 4 edges/thread via int4 (MLP=4)
// ---------------------------------------------------------------------------
__global__ void deg_count_kernel(const int* __restrict__ dst, int E) {
    int i = (blockIdx.x * blockDim.x + threadIdx.x) * 4;
    if (i + 3 < E) {
        int4 d = *(const int4*)(dst + i);
        atomicAdd(&g_deg[d.x], 1);
        atomicAdd(&g_deg[d.y], 1);
        atomicAdd(&g_deg[d.z], 1);
        atomicAdd(&g_deg[d.w], 1);
    } else {
        for (int j = i; j < E; j++) atomicAdd(&g_deg[dst[j]], 1);
    }
}

// ---------------------------------------------------------------------------
// Scan: block sums, then final scan (block prefix computed in-kernel)
// ---------------------------------------------------------------------------
__global__ void scan_bsum_kernel(int n) {
    __shared__ int sh[256];
    int b = blockIdx.x, t = threadIdx.x;
    int base = b * 1024;
    int s = 0;
    for (int i = t; i < 1024; i += 256) {
        int idx = base + i;
        if (idx < n) s += g_deg[idx];
    }
    sh[t] = s;
    __syncthreads();
    for (int o = 128; o > 0; o >>= 1) {
        if (t < o) sh[t] += sh[t + o];
        __syncthreads();
    }
    if (t == 0) g_bsum[b] = sh[0];
}

__global__ void scan_final_kernel(int n, int nb, int E) {
    __shared__ int sh[1024];
    __shared__ int pre[128];
    int b = blockIdx.x, t = threadIdx.x;

    if (t < 128) pre[t] = (t < b && t < nb) ? g_bsum[t] : 0;
    __syncthreads();
    if (t < 64) pre[t] += pre[t + 64];
    __syncthreads();
    if (t < 32) {
        int s = pre[t] + pre[t + 32];
#pragma unroll
        for (int o = 16; o > 0; o >>= 1)
            s += __shfl_down_sync(0xFFFFFFFFu, s, o);
        if (t == 0) pre[0] = s;
    }
    __syncthreads();
    const int bpre = pre[0];

    int idx = b * 1024 + t;
    int v = (idx < n) ? g_deg[idx] : 0;
    sh[t] = v;
    for (int o = 1; o < 1024; o <<= 1) {
        __syncthreads();
        int u = (t >= o) ? sh[t - o] : 0;
        __syncthreads();
        sh[t] += u;
    }
    __syncthreads();
    if (idx < n) {
        int ex = sh[t] - v + bpre;
        g_off[idx]    = ex;
        g_cursor[idx] = ex;
        g_dinv[idx]   = rsqrtf((float)(v + 1));
    }
    if (b == nb - 1 && t == 1023) g_off[n] = E;
}

// ---------------------------------------------------------------------------
// Edge pass 2: CSR fill — 4 edges/thread via int4 (MLP=4)
// ---------------------------------------------------------------------------
__global__ void fill_adj_kernel(const int* __restrict__ src,
                                const int* __restrict__ dst, int E) {
    int i = (blockIdx.x * blockDim.x + threadIdx.x) * 4;
    if (i + 3 < E) {
        int4 s = *(const int4*)(src + i);
        int4 d = *(const int4*)(dst + i);
        int p0 = atomicAdd(&g_cursor[d.x], 1);
        int p1 = atomicAdd(&g_cursor[d.y], 1);
        int p2 = atomicAdd(&g_cursor[d.z], 1);
        int p3 = atomicAdd(&g_cursor[d.w], 1);
        g_adj[p0] = s.x;
        g_adj[p1] = s.y;
        g_adj[p2] = s.z;
        g_adj[p3] = s.w;
    } else {
        for (int j = i; j < E; j++) {
            int pos = atomicAdd(&g_cursor[dst[j]], 1);
            g_adj[pos] = src[j];
        }
    }
}

// ---------------------------------------------------------------------------
// HMMA GEMM (proven): hs[row] = (transform(in[row]) @ W) * dinv[row]
// Split-bf16 3-pass, fp32 accumulation. Weights pre-split (global bf16).
// CTA tile 128x64, 512 threads = 16 warps (8x2 of 16x32 tiles).
// K=128: 2 CTAs/SM (smem-capped); K=64: 3 CTAs/SM.
// TRANS: BN params computed in-CTA from previous layer's g_sums slot.
// ---------------------------------------------------------------------------
template<int K, bool TRANS>
__global__ void __launch_bounds__(512, (K == 64) ? 3 : 2)
gemm_mma_kernel(const float* __restrict__ Xin,
                int woff, int soff,
                const float* __restrict__ gam,
                const float* __restrict__ bet,
                const float* __restrict__ alpha,
                int n)
{
    constexpr int LDA  = K + 8;
    constexpr int A_HI = 0;
    constexpr int A_LO = 128 * LDA;
    constexpr int B_HI = 256 * LDA;
    constexpr int B_LO = 256 * LDA + 64 * LDA;

    extern __shared__ __nv_bfloat16 smem[];
    __shared__ float sScale[64], sShift[64];
    const uint32_t sb = smem_u32(smem);
    const int tid = threadIdx.x;
    const int wid = tid >> 5, lid = tid & 31;
    const int rowBase = blockIdx.x * 128;

    if (TRANS) {
        if (tid < 64) {
            float sc, sh;
            bn_param(soff, tid, 1.0 / (double)n, gam, bet, sc, sh);
            sScale[tid] = sc;
            sShift[tid] = sh;
        }
        __syncthreads();
    }

    const float* X = TRANS ? g_acc : Xin;
    for (int i = tid; i < 128 * (K / 4); i += 512) {
        int r  = i / (K / 4);
        int k0 = (i % (K / 4)) * 4;
        float4 v = make_float4(0.f, 0.f, 0.f, 0.f);
        int row = rowBase + r;
        if (row < n) {
            v = *(const float4*)(X + (size_t)row * K + k0);
            if (TRANS) {
                float t;
                t = v.x * sScale[k0+0] + sShift[k0+0]; v.x = (t >= 0.f) ? t : t * alpha[k0+0];
                t = v.y * sScale[k0+1] + sShift[k0+1]; v.y = (t >= 0.f) ? t : t * alpha[k0+1];
                t = v.z * sScale[k0+2] + sShift[k0+2]; v.z = (t >= 0.f) ? t : t * alpha[k0+2];
                t = v.w * sScale[k0+3] + sShift[k0+3]; v.w = (t >= 0.f) ? t : t * alpha[k0+3];
            }
        }
        uint2 hi = split4(v);
        float4 res = make_float4(
            v.x - __bfloat162float(__float2bfloat16(v.x)),
            v.y - __bfloat162float(__float2bfloat16(v.y)),
            v.z - __bfloat162float(__float2bfloat16(v.z)),
            v.w - __bfloat162float(__float2bfloat16(v.w)));
        uint2 lo = split4(res);
        *(uint2*)(smem + A_HI + r * LDA + k0) = hi;
        *(uint2*)(smem + A_LO + r * LDA + k0) = lo;
    }

    for (int i = tid; i < 64 * (K / 8); i += 512) {
        int nn = i / (K / 8);
        int k0 = (i % (K / 8)) * 8;
        uint4 hi = *(const uint4*)(g_wThi + woff + nn * K + k0);
        uint4 lo = *(const uint4*)(g_wTlo + woff + nn * K + k0);
        *(uint4*)(smem + B_HI + nn * LDA + k0) = hi;
        *(uint4*)(smem + B_LO + nn * LDA + k0) = lo;
    }
    __syncthreads();

    const int warpRow = wid & 7;
    const int warpCol = wid >> 3;

    float acc[4][4];
#pragma unroll
    for (int ni = 0; ni < 4; ni++)
#pragma unroll
        for (int j = 0; j < 4; j++) acc[ni][j] = 0.f;

    const int aRow  = warpRow * 16 + (lid & 15);
    const int aKoff = (lid >> 4) * 8;
    const int bRow  = warpCol * 32 + (lid & 7);
    const int bKoff = ((lid >> 3) & 1) * 8;

#pragma unroll
    for (int k0 = 0; k0 < K; k0 += 16) {
        uint32_t aHi[4], aLo[4], bHi[4][2], bLo[4][2];
        {
            uint32_t base = (uint32_t)((aRow * LDA + k0 + aKoff) * 2);
            ldsm_x4(aHi, sb + A_HI * 2 + base);
            ldsm_x4(aLo, sb + A_LO * 2 + base);
        }
#pragma unroll
        for (int ni = 0; ni < 4; ni++) {
            uint32_t base = (uint32_t)(((bRow + ni * 8) * LDA + k0 + bKoff) * 2);
            ldsm_x2(bHi[ni], sb + B_HI * 2 + base);
            ldsm_x2(bLo[ni], sb + B_LO * 2 + base);
        }
#pragma unroll
        for (int ni = 0; ni < 4; ni++) {
            mma_bf16(acc[ni], aHi, bHi[ni]);
            mma_bf16(acc[ni], aHi, bLo[ni]);
            mma_bf16(acc[ni], aLo, bHi[ni]);
        }
    }

    const int rBase = rowBase + warpRow * 16 + (lid >> 2);
    const int cBase = warpCol * 32 + (lid & 3) * 2;
#pragma unroll
    for (int h = 0; h < 2; h++) {
        int row = rBase + h * 8;
        if (row < n) {
            float dv = g_dinv[row];
            __half* o = g_hs + (size_t)row * 64;
#pragma unroll
            for (int ni = 0; ni < 4; ni++) {
                float2 v = make_float2(acc[ni][h * 2 + 0] * dv,
                                       acc[ni][h * 2 + 1] * dv);
                *(__half2*)(o + cBase + ni * 8) = __float22half2_rn(v);
            }
        }
    }
}

// ---------------------------------------------------------------------------
// CSR gather (proven R13/R15): acc[v] = dinv[v] * (hs[v] + sum_{adj} hs[s])
// 8 threads per node; edge loop unrolled x4 with index prefetch (MLP=4).
// ---------------------------------------------------------------------------
__global__ void gather_kernel(int n)
{
    int idx = blockIdx.x * blockDim.x + threadIdx.x;
    int v = idx >> 3;
    int c = idx & 7;
    if (v >= n) return;
    int e0 = g_off[v];
    int e1 = g_off[v + 1];

    uint4 m = ((const uint4*)g_hs)[(size_t)v * 8 + c];  // self-loop
    float2 t0 = __half22float2(*(__half2*)&m.x);
    float2 t1 = __half22float2(*(__half2*)&m.y);
    float2 t2 = __half22float2(*(__half2*)&m.z);
    float2 t3 = __half22float2(*(__half2*)&m.w);

    int e = e0;
    for (; e + 4 <= e1; e += 4) {
        int s0 = __ldg(&g_adj[e + 0]);
        int s1 = __ldg(&g_adj[e + 1]);
        int s2 = __ldg(&g_adj[e + 2]);
        int s3 = __ldg(&g_adj[e + 3]);
        uint4 q0 = ((const uint4*)g_hs)[(size_t)s0 * 8 + c];
        uint4 q1 = ((const uint4*)g_hs)[(size_t)s1 * 8 + c];
        uint4 q2 = ((const uint4*)g_hs)[(size_t)s2 * 8 + c];
        uint4 q3 = ((const uint4*)g_hs)[(size_t)s3 * 8 + c];
        acc8(t0, t1, t2, t3, q0);
        acc8(t0, t1, t2, t3, q1);
        acc8(t0, t1, t2, t3, q2);
        acc8(t0, t1, t2, t3, q3);
    }
    for (; e < e1; e++) {
        int s = __ldg(&g_adj[e]);
        uint4 q = ((const uint4*)g_hs)[(size_t)s * 8 + c];
        acc8(t0, t1, t2, t3, q);
    }

    float dv = g_dinv[v];
    float4 o0 = make_float4(t0.x * dv, t0.y * dv, t1.x * dv, t1.y * dv);
    float4 o1 = make_float4(t2.x * dv, t2.y * dv, t3.x * dv, t3.y * dv);
    float4* out = (float4*)(g_acc + (size_t)v * 64 + c * 8);
    out[0] = o0;
    out[1] = o1;
}

// ---------------------------------------------------------------------------
// BN stats (proven): float4 per thread, 512 rows per block,
// writing into the given per-layer g_sums slot.
// ---------------------------------------------------------------------------
__global__ void stats_kernel(int n, int soff)
{
    __shared__ float4 sh1[256], sh2[256];
    int t  = threadIdx.x;
    int c  = t & 15;
    int rg = t >> 4;
    int r0   = blockIdx.x * 512;
    int rend = min(n, r0 + 512);
    float4 s1 = make_float4(0.f, 0.f, 0.f, 0.f);
    float4 s2 = make_float4(0.f, 0.f, 0.f, 0.f);
    for (int r = r0 + rg; r < rend; r += 16) {
        float4 v = ((const float4*)g_acc)[(size_t)r * 16 + c];
        s1.x += v.x; s1.y += v.y; s1.z += v.z; s1.w += v.w;
        s2.x += v.x * v.x; s2.y += v.y * v.y; s2.z += v.z * v.z; s2.w += v.w * v.w;
    }
    sh1[t] = s1; sh2[t] = s2;
    __syncthreads();
    if (t < 16) {
        float4 a1 = sh1[t], a2 = sh2[t];
#pragma unroll
        for (int g = 1; g < 16; g++) {
            float4 b1 = sh1[t + g * 16], b2 = sh2[t + g * 16];
            a1.x += b1.x; a1.y += b1.y; a1.z += b1.z; a1.w += b1.w;
            a2.x += b2.x; a2.y += b2.y; a2.z += b2.z; a2.w += b2.w;
        }
        int f = t * 4;
        atomicAdd(&g_sums[soff + f + 0], (double)a1.x);
        atomicAdd(&g_sums[soff + f + 1], (double)a1.y);
        atomicAdd(&g_sums[soff + f + 2], (double)a1.z);
        atomicAdd(&g_sums[soff + f + 3], (double)a1.w);
        atomicAdd(&g_sums[soff + 64 + f + 0], (double)a2.x);
        atomicAdd(&g_sums[soff + 64 + f + 1], (double)a2.y);
        atomicAdd(&g_sums[soff + 64 + f + 2], (double)a2.z);
        atomicAdd(&g_sums[soff + 64 + f + 3], (double)a2.w);
    }
}

// ---------------------------------------------------------------------------
// Output: computes layer-3 BN params in-block, applies BN+PReLU.
// ---------------------------------------------------------------------------
__global__ void out_kernel(const float* __restrict__ gam,
                           const float* __restrict__ bet,
                           const float* __restrict__ alpha,
                           float* __restrict__ out, int n)
{
    __shared__ float sS[64], sB[64];
    if (threadIdx.x < 64) {
        float sc, sh;
        bn_param(256, threadIdx.x, 1.0 / (double)n, gam, bet, sc, sh);
        sS[threadIdx.x] = sc;
        sB[threadIdx.x] = sh;
    }
    __syncthreads();

    int idx = blockIdx.x * blockDim.x + threadIdx.x;   // float4 chunk id
    if (idx >= n * 16) return;
    int f = (idx & 15) * 4;
    float4 v = ((const float4*)g_acc)[idx];
    float t;
    t = v.x * sS[f+0] + sB[f+0]; v.x = (t >= 0.f) ? t : t * alpha[f+0];
    t = v.y * sS[f+1] + sB[f+1]; v.y = (t >= 0.f) ? t : t * alpha[f+1];
    t = v.z * sS[f+2] + sB[f+2]; v.z = (t >= 0.f) ? t : t * alpha[f+2];
    t = v.w * sS[f+3] + sB[f+3]; v.w = (t >= 0.f) ? t : t * alpha[f+3];
    ((float4*)out)[idx] = v;
}

// ---------------------------------------------------------------------------
// Launch
// ---------------------------------------------------------------------------
extern "C" void kernel_launch(void* const* d_in, const int* in_sizes, int n_in,
                              void* d_out, int out_size)
{
    const float* x   = (const float*)d_in[0];
    const int*   ei  = (const int*)  d_in[1];
    const int N = in_sizes[0] / 128;
    const int E = in_sizes[1] / 2;
    const int* src = ei;
    const int* dst = ei + E;

    const float* W1  = (const float*)d_in[2];
    const float* G1  = (const float*)d_in[4];
    const float* BE1 = (const float*)d_in[5];
    const float* A1  = (const float*)d_in[6];
    const float* W2  = (const float*)d_in[7];
    const float* G2  = (const float*)d_in[9];
    const float* BE2 = (const float*)d_in[10];
    const float* A2  = (const float*)d_in[11];
    const float* W3  = (const float*)d_in[12];
    const float* G3  = (const float*)d_in[14];
    const float* BE3 = (const float*)d_in[15];
    const float* A3  = (const float*)d_in[16];

    const int smem128 = 384 * (128 + 8) * 2;  // 104448 B
    const int smem64  = 384 * (64 + 8) * 2;   //  55296 B
    cudaFuncSetAttribute((const void*)gemm_mma_kernel<128, false>,
                         cudaFuncAttributeMaxDynamicSharedMemorySize, smem128);
    cudaFuncSetAttribute((const void*)gemm_mma_kernel<64, true>,
                         cudaFuncAttributeMaxDynamicSharedMemorySize, smem64);

    const int gN  = (N + 255) / 256;
    const int gE4 = (E / 4 + 255) / 256;
    const int gG  = (N + 127) / 128;
    const int gGa = (N * 8 + 255) / 256;
    const int gS  = (N + 511) / 512;
    const int gO  = (N * 16 + 255) / 256;
    const int nb  = (N + 1023) / 1024;

    // Setup + CSR build (reused by all 3 layers)
    setup_kernel     <<<gN, 256>>>(W1, W2, W3, N);
    deg_count_kernel <<<gE4, 256>>>(dst, E);
    scan_bsum_kernel <<<nb, 256>>>(N);
    scan_final_kernel<<<nb, 1024>>>(N, nb, E);
    fill_adj_kernel  <<<gE4, 256>>>(src, dst, E);

    // ---- Layer 1 ----
    gemm_mma_kernel<128, false><<<gG, 512, smem128>>>(x, 0, 0, nullptr, nullptr, nullptr, N);
    gather_kernel   <<<gGa, 256>>>(N);
    stats_kernel    <<<gS, 256>>>(N, 0);

    // ---- Layer 2 (BN params of layer 1 computed in-GEMM from slot 0) ----
    gemm_mma_kernel<64, true><<<gG, 512, smem64>>>(nullptr, 8192, 0, G1, BE1, A1, N);
    gather_kernel   <<<gGa, 256>>>(N);
    stats_kernel    <<<gS, 256>>>(N, 128);

    // ---- Layer 3 (BN params of layer 2 from slot 1) ----
    gemm_mma_kernel<64, true><<<gG, 512, smem64>>>(nullptr, 12288, 128, G2, BE2, A2, N);
    gather_kernel   <<<gGa, 256>>>(N);
    stats_kernel    <<<gS, 256>>>(N, 256);

    // ---- Output (BN params of layer 3 from slot 2) ----
    out_kernel<<<gO, 256>>>(G3, BE3, A3, (float*)d_out, N);
}